// round 2
// baseline (speedup 1.0000x reference)
#include <cuda_runtime.h>
#include <cstdint>

#define BATCH 64
#define MROWS 2048
#define DIM   512

// Scratch: per-batch packed (dist_bits << 32) | (~m). No device allocation.
__device__ unsigned long long g_best[BATCH];

__global__ void knn_init_kernel() {
    int b = threadIdx.x;
    if (b < BATCH) g_best[b] = 0ULL;
}

// Grid: (MROWS/M_PER_BLOCK, BATCH). Block: 256 threads = 8 warps.
// Each warp computes squared L2 distance for 4 rows (M_PER_BLOCK=32 per block).
__global__ __launch_bounds__(256) void knn_dist_kernel(
    const float* __restrict__ inputs,
    const float* __restrict__ buffer)
{
    __shared__ float4 q4[DIM / 4];          // 2 KB query vector
    __shared__ unsigned long long wbest[8];

    const int b     = blockIdx.y;
    const int chunk = blockIdx.x;           // 0..63
    const int tid   = threadIdx.x;
    const int warp  = tid >> 5;
    const int lane  = tid & 31;

    // Stage query row into smem (coalesced float4)
    const float4* qin = reinterpret_cast<const float4*>(inputs + (size_t)b * DIM);
    for (int i = tid; i < DIM / 4; i += blockDim.x) q4[i] = qin[i];
    __syncthreads();

    const float* buf_b = buffer + (size_t)b * MROWS * DIM;

    unsigned long long local = 0ULL;
    #pragma unroll
    for (int k = 0; k < 4; k++) {
        const int m = chunk * 32 + warp * 4 + k;
        const float4* row = reinterpret_cast<const float4*>(buf_b + (size_t)m * DIM);
        float acc = 0.0f;
        #pragma unroll
        for (int j = 0; j < 4; j++) {
            const int idx = lane + 32 * j;   // coalesced: 128 consecutive float4 per warp
            float4 v = row[idx];
            float4 q = q4[idx];
            float d0 = v.x - q.x;
            float d1 = v.y - q.y;
            float d2 = v.z - q.z;
            float d3 = v.w - q.w;
            acc = fmaf(d0, d0, acc);
            acc = fmaf(d1, d1, acc);
            acc = fmaf(d2, d2, acc);
            acc = fmaf(d3, d3, acc);
        }
        // Warp sum reduction
        #pragma unroll
        for (int off = 16; off > 0; off >>= 1)
            acc += __shfl_xor_sync(0xFFFFFFFFu, acc, off);

        // dist^2 >= 0, so float bits are order-preserving as uint.
        // ~m in low bits: on equal distance, larger packed value = smaller m
        // (matches argmax first-index tie-break).
        unsigned long long pack =
            ((unsigned long long)__float_as_uint(acc) << 32) |
            (unsigned long long)(0xFFFFFFFFu - (unsigned)m);
        local = (pack > local) ? pack : local;
    }

    if (lane == 0) wbest[warp] = local;
    __syncthreads();

    if (tid == 0) {
        unsigned long long blk = wbest[0];
        #pragma unroll
        for (int w = 1; w < 8; w++)
            blk = (wbest[w] > blk) ? wbest[w] : blk;
        atomicMax(&g_best[b], blk);
    }
}

// Grid: BATCH blocks of 128 threads — copy the winning row to out.
__global__ void knn_gather_kernel(const float* __restrict__ buffer,
                                  float* __restrict__ out)
{
    const int b = blockIdx.x;
    const unsigned m = 0xFFFFFFFFu - (unsigned)(g_best[b] & 0xFFFFFFFFu);
    const float4* src =
        reinterpret_cast<const float4*>(buffer + ((size_t)b * MROWS + m) * DIM);
    float4* dst = reinterpret_cast<float4*>(out + (size_t)b * DIM);
    for (int i = threadIdx.x; i < DIM / 4; i += blockDim.x)
        dst[i] = src[i];
}

extern "C" void kernel_launch(void* const* d_in, const int* in_sizes, int n_in,
                              void* d_out, int out_size)
{
    const float* inputs = (const float*)d_in[0];   // [B, D]
    const float* buffer = (const float*)d_in[1];   // [B, M, D]
    float* out = (float*)d_out;                    // [B, D]

    knn_init_kernel<<<1, BATCH>>>();

    dim3 grid(MROWS / 32, BATCH);                  // 64 x 64 = 4096 blocks
    knn_dist_kernel<<<grid, 256>>>(inputs, buffer);

    knn_gather_kernel<<<BATCH, 128>>>(buffer, out);
}